// round 1
// baseline (speedup 1.0000x reference)
#include <cuda_runtime.h>

#define BATCH 8
#define DIM 256
#define SEQ 16384
#define KK 3
#define HID 85
#define OUTC (DIM*KK)
#define BN_EPS 1e-5f

// Scratch (device globals — no allocation allowed)
__device__ float g_pooled[BATCH * DIM];
__device__ float g_w[BATCH * OUTC];

// ---------------------------------------------------------------------------
// Kernel 1: mean over seq for each (b, c) row. grid=(DIM, BATCH), block=256
// ---------------------------------------------------------------------------
__global__ void pool_kernel(const float* __restrict__ x) {
    const int c = blockIdx.x;
    const int b = blockIdx.y;
    const size_t rowoff = ((size_t)b * DIM + c) * SEQ;
    const float4* row = (const float4*)(x + rowoff);

    float s = 0.f;
    #pragma unroll 4
    for (int i = threadIdx.x; i < SEQ / 4; i += 256) {
        float4 v = row[i];
        s += (v.x + v.y) + (v.z + v.w);
    }

    __shared__ float sm[256];
    sm[threadIdx.x] = s;
    __syncthreads();
    for (int off = 128; off > 0; off >>= 1) {
        if (threadIdx.x < off) sm[threadIdx.x] += sm[threadIdx.x + off];
        __syncthreads();
    }
    if (threadIdx.x == 0) g_pooled[b * DIM + c] = sm[0] * (1.f / SEQ);
}

// ---------------------------------------------------------------------------
// Kernel 2: tiny MLP per batch. grid=(BATCH), block=256
//   y = relu((w1 @ pooled - mean) * gamma * rsqrt(var+eps) + beta)   [HID]
//   w = w2 @ y + b2                                                  [OUTC]
// ---------------------------------------------------------------------------
__global__ void mlp_kernel(const float* __restrict__ w1,
                           const float* __restrict__ gamma,
                           const float* __restrict__ beta,
                           const float* __restrict__ mean,
                           const float* __restrict__ var,
                           const float* __restrict__ w2,
                           const float* __restrict__ b2) {
    const int b = blockIdx.x;
    const int tid = threadIdx.x;

    __shared__ float ps[DIM];
    __shared__ float ys[HID];

    ps[tid] = g_pooled[b * DIM + tid];
    __syncthreads();

    if (tid < HID) {
        const float* wr = w1 + tid * DIM;
        float acc = 0.f;
        #pragma unroll 8
        for (int c = 0; c < DIM; c++) acc = fmaf(wr[c], ps[c], acc);
        float v = (acc - mean[tid]) * (gamma[tid] * rsqrtf(var[tid] + BN_EPS)) + beta[tid];
        ys[tid] = fmaxf(v, 0.f);
    }
    __syncthreads();

    for (int o = tid; o < OUTC; o += 256) {
        const float* wr = w2 + o * HID;
        float acc = b2[o];
        #pragma unroll 5
        for (int h = 0; h < HID; h++) acc = fmaf(wr[h], ys[h], acc);
        g_w[b * OUTC + o] = acc;
    }
}

// ---------------------------------------------------------------------------
// Kernel 3: depthwise 3-tap conv with pad=1 + bias.
// grid=(SEQ/4/256, DIM, BATCH), block=256. One float4 per thread.
// ---------------------------------------------------------------------------
__global__ void conv_kernel(const float* __restrict__ x,
                            const float* __restrict__ bias,
                            float* __restrict__ out) {
    const int b = blockIdx.z;
    const int c = blockIdx.y;
    const int t4 = blockIdx.x * blockDim.x + threadIdx.x;   // float4 index in row
    const size_t rowoff = ((size_t)b * DIM + c) * SEQ;

    const float w0 = g_w[b * OUTC + c * KK + 0];
    const float w1v = g_w[b * OUTC + c * KK + 1];
    const float w2v = g_w[b * OUTC + c * KK + 2];
    const float bb = __ldg(bias + c);

    const float4 xc = *(const float4*)(x + rowoff + (size_t)t4 * 4);
    const int t0 = t4 * 4;
    const float xl = (t0 == 0)        ? 0.f : __ldg(x + rowoff + t0 - 1);
    const float xr = (t0 + 4 >= SEQ)  ? 0.f : __ldg(x + rowoff + t0 + 4);

    float4 o;
    o.x = fmaf(w0, xl,   fmaf(w1v, xc.x, fmaf(w2v, xc.y, bb)));
    o.y = fmaf(w0, xc.x, fmaf(w1v, xc.y, fmaf(w2v, xc.z, bb)));
    o.z = fmaf(w0, xc.y, fmaf(w1v, xc.z, fmaf(w2v, xc.w, bb)));
    o.w = fmaf(w0, xc.z, fmaf(w1v, xc.w, fmaf(w2v, xr,   bb)));

    *(float4*)(out + rowoff + (size_t)t4 * 4) = o;
}

// ---------------------------------------------------------------------------
// Launch. Inputs (metadata order): x, w1, bn_gamma, bn_beta, bn_mean, bn_var,
// w2, b2, bias. Output: fp32 [8, 256, 16384].
// ---------------------------------------------------------------------------
extern "C" void kernel_launch(void* const* d_in, const int* in_sizes, int n_in,
                              void* d_out, int out_size) {
    const float* x     = (const float*)d_in[0];
    const float* w1    = (const float*)d_in[1];
    const float* gamma = (const float*)d_in[2];
    const float* beta  = (const float*)d_in[3];
    const float* mean  = (const float*)d_in[4];
    const float* var   = (const float*)d_in[5];
    const float* w2    = (const float*)d_in[6];
    const float* b2    = (const float*)d_in[7];
    const float* bias  = (const float*)d_in[8];
    float* out = (float*)d_out;

    dim3 pg(DIM, BATCH);
    pool_kernel<<<pg, 256>>>(x);

    mlp_kernel<<<BATCH, 256>>>(w1, gamma, beta, mean, var, w2, b2);

    dim3 cg(SEQ / 4 / 256, DIM, BATCH);
    conv_kernel<<<cg, 256>>>(x, bias, out);
}

// round 2
// speedup vs baseline: 1.2972x; 1.2972x over previous
#include <cuda_runtime.h>

#define BATCH 8
#define DIM 256
#define SEQ 16384
#define KK 3
#define HID 85
#define OUTC (DIM*KK)
#define BN_EPS 1e-5f
#define FULLM 0xffffffffu

// Scratch (device globals — no allocation allowed)
__device__ float g_pooled[BATCH * DIM];
__device__ float g_w[BATCH * OUTC];

// ---------------------------------------------------------------------------
// Kernel 1: mean over seq for each (b, c) row. grid=(DIM, BATCH), block=256
// ---------------------------------------------------------------------------
__global__ void pool_kernel(const float* __restrict__ x) {
    const int c = blockIdx.x;
    const int b = blockIdx.y;
    const size_t rowoff = ((size_t)b * DIM + c) * SEQ;
    const float4* row = (const float4*)(x + rowoff);

    float s0 = 0.f, s1 = 0.f;
    #pragma unroll 8
    for (int i = threadIdx.x; i < SEQ / 4; i += 512) {
        float4 a = row[i];
        float4 bb = row[i + 256];
        s0 += (a.x + a.y) + (a.z + a.w);
        s1 += (bb.x + bb.y) + (bb.z + bb.w);
    }
    float s = s0 + s1;

    // warp reduce, then cross-warp via smem
    #pragma unroll
    for (int off = 16; off > 0; off >>= 1)
        s += __shfl_down_sync(FULLM, s, off);

    __shared__ float sm[8];
    if ((threadIdx.x & 31) == 0) sm[threadIdx.x >> 5] = s;
    __syncthreads();
    if (threadIdx.x < 8) {
        float v = sm[threadIdx.x];
        #pragma unroll
        for (int off = 4; off > 0; off >>= 1)
            v += __shfl_down_sync(0xffu, v, off);
        if (threadIdx.x == 0) g_pooled[b * DIM + c] = v * (1.f / SEQ);
    }
}

// ---------------------------------------------------------------------------
// Kernel 2: tiny MLP. grid=(4, BATCH), block=256.
// Each block redundantly computes y[HID] for its batch, then 192 of the 768
// outputs (chunk = blockIdx.x). 32 blocks total -> w2 load latency hidden.
// ---------------------------------------------------------------------------
__global__ void mlp_kernel(const float* __restrict__ w1,
                           const float* __restrict__ gamma,
                           const float* __restrict__ beta,
                           const float* __restrict__ mean,
                           const float* __restrict__ var,
                           const float* __restrict__ w2,
                           const float* __restrict__ b2) {
    const int b = blockIdx.y;
    const int chunk = blockIdx.x;          // 0..3, 192 outputs each
    const int tid = threadIdx.x;

    __shared__ float ps[DIM];
    __shared__ float ys[HID];

    ps[tid] = g_pooled[b * DIM + tid];
    __syncthreads();

    if (tid < HID) {
        const float* wr = w1 + tid * DIM;
        float acc = 0.f;
        #pragma unroll 8
        for (int c = 0; c < DIM; c++) acc = fmaf(wr[c], ps[c], acc);
        float v = (acc - mean[tid]) * (gamma[tid] * rsqrtf(var[tid] + BN_EPS)) + beta[tid];
        ys[tid] = fmaxf(v, 0.f);
    }
    __syncthreads();

    const int o = chunk * 192 + tid;
    if (tid < 192) {
        const float* wr = w2 + o * HID;
        float acc = b2[o];
        #pragma unroll 5
        for (int h = 0; h < HID; h++) acc = fmaf(wr[h], ys[h], acc);
        g_w[b * OUTC + o] = acc;
    }
}

// ---------------------------------------------------------------------------
// Kernel 3: depthwise 3-tap conv, pad=1, + bias.
// grid=(8, DIM, BATCH), block=256. Each thread: 2 float4s (positions p and
// p+2048 within the row's 4096 float4s). Boundary neighbors via warp shuffle
// (lanes are consecutive float4s); only lanes 0/31 issue a scalar load.
// Block coords REVERSED so conv starts on the tail of x that pool left in L2.
// ---------------------------------------------------------------------------
__global__ void conv_kernel(const float* __restrict__ x,
                            const float* __restrict__ bias,
                            float* __restrict__ out) {
    const int b = (BATCH - 1) - blockIdx.z;
    const int c = (DIM - 1) - blockIdx.y;
    const int chunk = (int)(gridDim.x - 1) - blockIdx.x;     // 0..7
    const int tid = threadIdx.x;
    const int lane = tid & 31;
    const size_t rowoff = ((size_t)b * DIM + c) * SEQ;

    const float w0 = g_w[b * OUTC + c * KK + 0];
    const float w1v = g_w[b * OUTC + c * KK + 1];
    const float w2v = g_w[b * OUTC + c * KK + 2];
    const float bb = __ldg(bias + c);

    const int p0 = chunk * 256 + tid;          // float4 idx, first half
    const int p1 = p0 + 2048;                  // second half
    const int t0 = p0 * 4;
    const int t1 = p1 * 4;

    // issue both main loads first (2 independent chains)
    const float4 xa = *(const float4*)(x + rowoff + t0);
    const float4 xb = *(const float4*)(x + rowoff + t1);

    float xla = __shfl_up_sync(FULLM, xa.w, 1);
    float xra = __shfl_down_sync(FULLM, xa.x, 1);
    float xlb = __shfl_up_sync(FULLM, xb.w, 1);
    float xrb = __shfl_down_sync(FULLM, xb.x, 1);

    if (lane == 0) {
        xla = (t0 == 0) ? 0.f : __ldg(x + rowoff + t0 - 1);
        xlb = __ldg(x + rowoff + t1 - 1);
    }
    if (lane == 31) {
        xra = __ldg(x + rowoff + t0 + 4);
        xrb = (t1 + 4 >= SEQ) ? 0.f : __ldg(x + rowoff + t1 + 4);
    }

    float4 oa, ob;
    oa.x = fmaf(w0, xla,  fmaf(w1v, xa.x, fmaf(w2v, xa.y, bb)));
    oa.y = fmaf(w0, xa.x, fmaf(w1v, xa.y, fmaf(w2v, xa.z, bb)));
    oa.z = fmaf(w0, xa.y, fmaf(w1v, xa.z, fmaf(w2v, xa.w, bb)));
    oa.w = fmaf(w0, xa.z, fmaf(w1v, xa.w, fmaf(w2v, xra,  bb)));

    ob.x = fmaf(w0, xlb,  fmaf(w1v, xb.x, fmaf(w2v, xb.y, bb)));
    ob.y = fmaf(w0, xb.x, fmaf(w1v, xb.y, fmaf(w2v, xb.z, bb)));
    ob.z = fmaf(w0, xb.y, fmaf(w1v, xb.z, fmaf(w2v, xb.w, bb)));
    ob.w = fmaf(w0, xb.z, fmaf(w1v, xb.w, fmaf(w2v, xrb,  bb)));

    *(float4*)(out + rowoff + t0) = oa;
    *(float4*)(out + rowoff + t1) = ob;
}

// ---------------------------------------------------------------------------
// Launch. Inputs (metadata order): x, w1, bn_gamma, bn_beta, bn_mean, bn_var,
// w2, b2, bias. Output: fp32 [8, 256, 16384].
// ---------------------------------------------------------------------------
extern "C" void kernel_launch(void* const* d_in, const int* in_sizes, int n_in,
                              void* d_out, int out_size) {
    const float* x     = (const float*)d_in[0];
    const float* w1    = (const float*)d_in[1];
    const float* gamma = (const float*)d_in[2];
    const float* beta  = (const float*)d_in[3];
    const float* mean  = (const float*)d_in[4];
    const float* var   = (const float*)d_in[5];
    const float* w2    = (const float*)d_in[6];
    const float* b2    = (const float*)d_in[7];
    const float* bias  = (const float*)d_in[8];
    float* out = (float*)d_out;

    dim3 pg(DIM, BATCH);
    pool_kernel<<<pg, 256>>>(x);

    dim3 mg(4, BATCH);
    mlp_kernel<<<mg, 256>>>(w1, gamma, beta, mean, var, w2, b2);

    dim3 cg(8, DIM, BATCH);
    conv_kernel<<<cg, 256>>>(x, bias, out);
}

// round 3
// speedup vs baseline: 1.3349x; 1.0291x over previous
#include <cuda_runtime.h>

#define BATCH 8
#define DIM 256
#define SEQ 16384
#define KK 3
#define HID 85
#define OUTC (DIM*KK)
#define BN_EPS 1e-5f
#define FULLM 0xffffffffu

// Scratch (device globals — no allocation allowed)
__device__ float g_pooled[BATCH * DIM];
__device__ float g_w[BATCH * OUTC];

// ---------------------------------------------------------------------------
// Kernel 1: mean over seq for each (b, c) row. grid=(DIM, BATCH), block=512.
// 8 front-batched float4 loads per thread (high MLP), full unroll.
// ---------------------------------------------------------------------------
__global__ void pool_kernel(const float* __restrict__ x) {
    const int c = blockIdx.x;
    const int b = blockIdx.y;
    const size_t rowoff = ((size_t)b * DIM + c) * SEQ;
    const float4* row = (const float4*)(x + rowoff);

    float4 v[8];
    #pragma unroll
    for (int j = 0; j < 8; j++)
        v[j] = row[threadIdx.x + j * 512];

    float s = 0.f;
    #pragma unroll
    for (int j = 0; j < 8; j++)
        s += (v[j].x + v[j].y) + (v[j].z + v[j].w);

    // warp reduce, then cross-warp via smem
    #pragma unroll
    for (int off = 16; off > 0; off >>= 1)
        s += __shfl_down_sync(FULLM, s, off);

    __shared__ float sm[16];
    if ((threadIdx.x & 31) == 0) sm[threadIdx.x >> 5] = s;
    __syncthreads();
    if (threadIdx.x < 16) {
        float t = sm[threadIdx.x];
        #pragma unroll
        for (int off = 8; off > 0; off >>= 1)
            t += __shfl_down_sync(0xffffu, t, off);
        if (threadIdx.x == 0) g_pooled[b * DIM + c] = t * (1.f / SEQ);
    }
}

// ---------------------------------------------------------------------------
// Kernel 2: tiny MLP. grid=(4, BATCH), block=256.
// Each block redundantly computes y[HID] for its batch, then 192 of the 768
// outputs (chunk = blockIdx.x).
// ---------------------------------------------------------------------------
__global__ void mlp_kernel(const float* __restrict__ w1,
                           const float* __restrict__ gamma,
                           const float* __restrict__ beta,
                           const float* __restrict__ mean,
                           const float* __restrict__ var,
                           const float* __restrict__ w2,
                           const float* __restrict__ b2) {
    const int b = blockIdx.y;
    const int chunk = blockIdx.x;          // 0..3, 192 outputs each
    const int tid = threadIdx.x;

    __shared__ float ps[DIM];
    __shared__ float ys[HID];

    ps[tid] = g_pooled[b * DIM + tid];
    __syncthreads();

    if (tid < HID) {
        const float* wr = w1 + tid * DIM;
        float acc = 0.f;
        #pragma unroll 8
        for (int c = 0; c < DIM; c++) acc = fmaf(wr[c], ps[c], acc);
        float v = (acc - mean[tid]) * (gamma[tid] * rsqrtf(var[tid] + BN_EPS)) + beta[tid];
        ys[tid] = fmaxf(v, 0.f);
    }
    __syncthreads();

    const int o = chunk * 192 + tid;
    if (tid < 192) {
        const float* wr = w2 + o * HID;
        float acc = b2[o];
        #pragma unroll 5
        for (int h = 0; h < HID; h++) acc = fmaf(wr[h], ys[h], acc);
        g_w[b * OUTC + o] = acc;
    }
}

// ---------------------------------------------------------------------------
// Kernel 3: depthwise 3-tap conv, pad=1, + bias.
// grid=(8, DIM, BATCH), block=256. Each thread: 2 float4s. Halo via shuffle.
// Reversed traversal (tail of x is freshest in L2 after pool).
// out is written with STREAMING stores (__stcs, evict-first) so the 134 MB
// output stream does not evict x from L2 — x's second read should mostly hit.
// ---------------------------------------------------------------------------
__global__ void conv_kernel(const float* __restrict__ x,
                            const float* __restrict__ bias,
                            float* __restrict__ out) {
    const int b = (BATCH - 1) - blockIdx.z;
    const int c = (DIM - 1) - blockIdx.y;
    const int chunk = (int)(gridDim.x - 1) - blockIdx.x;     // 0..7
    const int tid = threadIdx.x;
    const int lane = tid & 31;
    const size_t rowoff = ((size_t)b * DIM + c) * SEQ;

    const float w0 = g_w[b * OUTC + c * KK + 0];
    const float w1v = g_w[b * OUTC + c * KK + 1];
    const float w2v = g_w[b * OUTC + c * KK + 2];
    const float bb = __ldg(bias + c);

    const int p0 = chunk * 256 + tid;          // float4 idx, first half
    const int p1 = p0 + 2048;                  // second half
    const int t0 = p0 * 4;
    const int t1 = p1 * 4;

    const float4 xa = *(const float4*)(x + rowoff + t0);
    const float4 xb = *(const float4*)(x + rowoff + t1);

    float xla = __shfl_up_sync(FULLM, xa.w, 1);
    float xra = __shfl_down_sync(FULLM, xa.x, 1);
    float xlb = __shfl_up_sync(FULLM, xb.w, 1);
    float xrb = __shfl_down_sync(FULLM, xb.x, 1);

    if (lane == 0) {
        xla = (t0 == 0) ? 0.f : __ldg(x + rowoff + t0 - 1);
        xlb = __ldg(x + rowoff + t1 - 1);
    }
    if (lane == 31) {
        xra = __ldg(x + rowoff + t0 + 4);
        xrb = (t1 + 4 >= SEQ) ? 0.f : __ldg(x + rowoff + t1 + 4);
    }

    float4 oa, ob;
    oa.x = fmaf(w0, xla,  fmaf(w1v, xa.x, fmaf(w2v, xa.y, bb)));
    oa.y = fmaf(w0, xa.x, fmaf(w1v, xa.y, fmaf(w2v, xa.z, bb)));
    oa.z = fmaf(w0, xa.y, fmaf(w1v, xa.z, fmaf(w2v, xa.w, bb)));
    oa.w = fmaf(w0, xa.z, fmaf(w1v, xa.w, fmaf(w2v, xra,  bb)));

    ob.x = fmaf(w0, xlb,  fmaf(w1v, xb.x, fmaf(w2v, xb.y, bb)));
    ob.y = fmaf(w0, xb.x, fmaf(w1v, xb.y, fmaf(w2v, xb.z, bb)));
    ob.z = fmaf(w0, xb.y, fmaf(w1v, xb.z, fmaf(w2v, xb.w, bb)));
    ob.w = fmaf(w0, xb.z, fmaf(w1v, xb.w, fmaf(w2v, xrb,  bb)));

    __stcs((float4*)(out + rowoff + t0), oa);
    __stcs((float4*)(out + rowoff + t1), ob);
}

// ---------------------------------------------------------------------------
// Launch. Inputs (metadata order): x, w1, bn_gamma, bn_beta, bn_mean, bn_var,
// w2, b2, bias. Output: fp32 [8, 256, 16384].
// ---------------------------------------------------------------------------
extern "C" void kernel_launch(void* const* d_in, const int* in_sizes, int n_in,
                              void* d_out, int out_size) {
    const float* x     = (const float*)d_in[0];
    const float* w1    = (const float*)d_in[1];
    const float* gamma = (const float*)d_in[2];
    const float* beta  = (const float*)d_in[3];
    const float* mean  = (const float*)d_in[4];
    const float* var   = (const float*)d_in[5];
    const float* w2    = (const float*)d_in[6];
    const float* b2    = (const float*)d_in[7];
    const float* bias  = (const float*)d_in[8];
    float* out = (float*)d_out;

    dim3 pg(DIM, BATCH);
    pool_kernel<<<pg, 512>>>(x);

    dim3 mg(4, BATCH);
    mlp_kernel<<<mg, 256>>>(w1, gamma, beta, mean, var, w2, b2);

    dim3 cg(8, DIM, BATCH);
    conv_kernel<<<cg, 256>>>(x, bias, out);
}